// round 12
// baseline (speedup 1.0000x reference)
#include <cuda_runtime.h>
#include <math.h>

#define BLOCK 64
#define MAXBLOCKS 256

__device__ float2 g_partials[MAXBLOCKS];
__device__ unsigned int g_count = 0;

// Shoelace line-integral contribution of the 4 CCW edges of polygon P (world
// coords) clipped to the inside of an oriented box (center cx,cy; half
// extents hx,hy; frame cos/sin c,s). Liang-Barsky in the box's local frame;
// t is frame-invariant so endpoints are recovered in world coords.
__device__ __forceinline__ float edges_clip_acc(
    const float* Px, const float* Py,
    float cx, float cy, float hx, float hy, float c, float s)
{
    float acc = 0.0f;
#pragma unroll
    for (int i = 0; i < 4; i++) {
        float p0x = Px[i],           p0y = Py[i];
        float p1x = Px[(i + 1) & 3], p1y = Py[(i + 1) & 3];

        float r0x = p0x - cx, r0y = p0y - cy;
        float q0x =  r0x * c + r0y * s;
        float q0y = -r0x * s + r0y * c;
        float r1x = p1x - cx, r1y = p1y - cy;
        float q1x =  r1x * c + r1y * s;
        float q1y = -r1x * s + r1y * c;

        float dx = q1x - q0x, dy = q1y - q0y;

        // slab clip: division by ~0 yields +-inf which fmin/fmax handle;
        // 0/0 NaNs are neutralized by CUDA fmin/fmax semantics.
        float ta = __fdividef(-hx - q0x, dx);
        float tb = __fdividef( hx - q0x, dx);
        float txmin = fminf(ta, tb), txmax = fmaxf(ta, tb);
        ta = __fdividef(-hy - q0y, dy);
        tb = __fdividef( hy - q0y, dy);
        float tymin = fminf(ta, tb), tymax = fmaxf(ta, tb);

        float te = fmaxf(fmaxf(txmin, tymin), 0.0f);
        float tx = fminf(fminf(txmax, tymax), 1.0f);

        if (te < tx) {
            float ex = p1x - p0x, ey = p1y - p0y;
            float ax = p0x + te * ex, ay = p0y + te * ey;
            float bx2 = p0x + tx * ex, by2 = p0y + tx * ey;
            acc += ax * by2 - ay * bx2;
        }
    }
    return acc;
}

// BEV intersection area via Green's theorem: boundary of A cap B =
// (edges of A inside B) + (edges of B inside A); the shoelace integral is
// additive over directed boundary segments. Register-only, no sort/atan2.
__device__ __forceinline__ float bev_inter(
    float ax, float ay, float adx, float ady, float ah,
    float bx, float by, float bdx, float bdy, float bh)
{
    float ac, as, bc, bs;
    __sincosf(ah, &as, &ac);
    __sincosf(bh, &bs, &bc);

    const float CTX[4] = {0.5f, -0.5f, -0.5f, 0.5f};
    const float CTY[4] = {0.5f, 0.5f, -0.5f, -0.5f};

    float cax[4], cay[4], cbx[4], cby[4];
#pragma unroll
    for (int i = 0; i < 4; i++) {
        float lx = CTX[i] * adx, ly = CTY[i] * ady;
        cax[i] = lx * ac - ly * as + ax;
        cay[i] = lx * as + ly * ac + ay;
        lx = CTX[i] * bdx; ly = CTY[i] * bdy;
        cbx[i] = lx * bc - ly * bs + bx;
        cby[i] = lx * bs + ly * bc + by;
    }

    float acc = edges_clip_acc(cax, cay, bx, by, 0.5f * bdx, 0.5f * bdy, bc, bs)
              + edges_clip_acc(cbx, cby, ax, ay, 0.5f * adx, 0.5f * ady, ac, as);
    return 0.5f * fabsf(acc);
}

__global__ void __launch_bounds__(BLOCK)
iou_loss_fused(const float* __restrict__ iou_pred,
               const int* __restrict__ mask,
               const int* __restrict__ ind,
               const float* __restrict__ box_pred,
               const float* __restrict__ box_gt,
               int M, int HW, int total,
               float* __restrict__ out, int out_size)
{
    int tid = blockIdx.x * BLOCK + threadIdx.x;
    float num = 0.0f, den = 0.0f;

    if (tid < total) {
        // all loads issued up front, unconditionally: mask never gates a
        // load, so the only serial chain is ind -> scattered gather.
        int mm  = mask[tid];
        int idx = ind[tid];
        int b = tid / M;

        float gb[7];
        const float* gp = box_gt + (size_t)tid * 7;
#pragma unroll
        for (int d = 0; d < 7; d++) gb[d] = gp[d];

        const float* bp = box_pred + (size_t)b * 7 * HW + idx;
        float pred = iou_pred[(size_t)b * HW + idx];
        float pb[7];
#pragma unroll
        for (int d = 0; d < 7; d++) pb[d] = bp[(size_t)d * HW];

        if (mm != 0) {
            // exact quick reject: separated bounding circles -> every edge
            // clips to an empty segment -> inter_bev exactly 0.
            float dx = pb[0] - gb[0], dy = pb[1] - gb[1];
            float ra2 = pb[3] * pb[3] + pb[4] * pb[4];
            float rb2 = gb[3] * gb[3] + gb[4] * gb[4];
            float rr = 0.5f * (__fsqrt_rn(ra2) + __fsqrt_rn(rb2)) + 1e-3f;

            float target;
            if (dx * dx + dy * dy > rr * rr) {
                target = -1.0f;   // iou = 0 -> 2*0-1
            } else {
                float inter_bev = bev_inter(pb[0], pb[1], pb[3], pb[4], pb[6],
                                            gb[0], gb[1], gb[3], gb[4], gb[6]);
                float top = fminf(pb[2] + pb[5] * 0.5f, gb[2] + gb[5] * 0.5f);
                float bot = fmaxf(pb[2] - pb[5] * 0.5f, gb[2] - gb[5] * 0.5f);
                float inter = inter_bev * fmaxf(top - bot, 0.0f);
                float va = pb[3] * pb[4] * pb[5];
                float vb = gb[3] * gb[4] * gb[5];
                float iou = inter / fmaxf(va + vb - inter, 1e-6f);
                target = 2.0f * iou - 1.0f;
            }

            num = fabsf(pred - target);
            den = 1.0f;
        }
    }

    // warp reduce
#pragma unroll
    for (int off = 16; off > 0; off >>= 1) {
        num += __shfl_down_sync(0xffffffffu, num, off);
        den += __shfl_down_sync(0xffffffffu, den, off);
    }
    __shared__ float2 swarp[BLOCK / 32];
    __shared__ bool s_last;
    int lane = threadIdx.x & 31, wid = threadIdx.x >> 5;
    if (lane == 0) swarp[wid] = make_float2(num, den);
    __syncthreads();

    if (threadIdx.x == 0) {
        float2 acc = swarp[0];
#pragma unroll
        for (int w = 1; w < BLOCK / 32; w++) {
            acc.x += swarp[w].x; acc.y += swarp[w].y;
        }
        g_partials[blockIdx.x] = acc;
        __threadfence();
        unsigned int v = atomicAdd(&g_count, 1u);
        s_last = (v == gridDim.x - 1);
    }
    __syncthreads();

    // last-finishing block: warp 0 alone reduces partials and writes out
    if (s_last && wid == 0) {
        float pn = 0.0f, pd = 0.0f;
        for (int i = lane; i < (int)gridDim.x; i += 32) {
            float2 p = g_partials[i];
            pn += p.x; pd += p.y;
        }
#pragma unroll
        for (int off = 16; off > 0; off >>= 1) {
            pn += __shfl_down_sync(0xffffffffu, pn, off);
            pd += __shfl_down_sync(0xffffffffu, pd, off);
        }
        if (lane == 0) {
            float loss = pn / (pd + 1e-4f);
            for (int i = 0; i < out_size; i++) out[i] = loss;
            g_count = 0;  // reset for next graph replay
        }
    }
}

extern "C" void kernel_launch(void* const* d_in, const int* in_sizes, int n_in,
                              void* d_out, int out_size)
{
    const float* iou_pred = (const float*)d_in[0];  // (B,1,H,W)
    const int*   mask     = (const int*)d_in[1];    // (B,M)
    const int*   ind      = (const int*)d_in[2];    // (B,M)
    const float* box_pred = (const float*)d_in[3];  // (B,7,H,W)
    const float* box_gt   = (const float*)d_in[4];  // (B,M,7)

    const int B = 16;
    int BM = in_sizes[1];     // B*M
    int M = BM / B;
    int HW = in_sizes[0] / B; // C == 1

    int total = BM;
    int nblocks = (total + BLOCK - 1) / BLOCK;
    if (nblocks > MAXBLOCKS) nblocks = MAXBLOCKS;  // 8000/64 = 125

    iou_loss_fused<<<nblocks, BLOCK>>>(iou_pred, mask, ind, box_pred, box_gt,
                                       M, HW, total, (float*)d_out, out_size);
}

// round 13
// speedup vs baseline: 1.0332x; 1.0332x over previous
#include <cuda_runtime.h>
#include <math.h>

#define BLOCK 64
#define MAXBLOCKS 256

__device__ float2 g_partials[MAXBLOCKS];
__device__ unsigned int g_count = 0;

// Shoelace line-integral contribution of the 4 CCW edges of polygon P (world
// coords) clipped to the inside of an oriented box (center cx,cy; half
// extents hx,hy; frame cos/sin c,s). Liang-Barsky in the box's local frame;
// t is frame-invariant so endpoints are recovered in world coords.
__device__ __forceinline__ float edges_clip_acc(
    const float* Px, const float* Py,
    float cx, float cy, float hx, float hy, float c, float s)
{
    float acc = 0.0f;
#pragma unroll
    for (int i = 0; i < 4; i++) {
        float p0x = Px[i],           p0y = Py[i];
        float p1x = Px[(i + 1) & 3], p1y = Py[(i + 1) & 3];

        float r0x = p0x - cx, r0y = p0y - cy;
        float q0x =  r0x * c + r0y * s;
        float q0y = -r0x * s + r0y * c;
        float r1x = p1x - cx, r1y = p1y - cy;
        float q1x =  r1x * c + r1y * s;
        float q1y = -r1x * s + r1y * c;

        float dx = q1x - q0x, dy = q1y - q0y;

        // slab clip: division by ~0 yields +-inf which fmin/fmax handle;
        // 0/0 NaNs are neutralized by CUDA fmin/fmax semantics.
        float ta = __fdividef(-hx - q0x, dx);
        float tb = __fdividef( hx - q0x, dx);
        float txmin = fminf(ta, tb), txmax = fmaxf(ta, tb);
        ta = __fdividef(-hy - q0y, dy);
        tb = __fdividef( hy - q0y, dy);
        float tymin = fminf(ta, tb), tymax = fmaxf(ta, tb);

        float te = fmaxf(fmaxf(txmin, tymin), 0.0f);
        float tx = fminf(fminf(txmax, tymax), 1.0f);

        if (te < tx) {
            float ex = p1x - p0x, ey = p1y - p0y;
            float ax = p0x + te * ex, ay = p0y + te * ey;
            float bx2 = p0x + tx * ex, by2 = p0y + tx * ey;
            acc += ax * by2 - ay * bx2;
        }
    }
    return acc;
}

// BEV intersection area via Green's theorem: boundary of A cap B =
// (edges of A inside B) + (edges of B inside A); the shoelace integral is
// additive over directed boundary segments. Register-only, no sort/atan2.
__device__ __forceinline__ float bev_inter(
    float ax, float ay, float adx, float ady, float ah,
    float bx, float by, float bdx, float bdy, float bh)
{
    float ac, as, bc, bs;
    __sincosf(ah, &as, &ac);
    __sincosf(bh, &bs, &bc);

    const float CTX[4] = {0.5f, -0.5f, -0.5f, 0.5f};
    const float CTY[4] = {0.5f, 0.5f, -0.5f, -0.5f};

    float cax[4], cay[4], cbx[4], cby[4];
#pragma unroll
    for (int i = 0; i < 4; i++) {
        float lx = CTX[i] * adx, ly = CTY[i] * ady;
        cax[i] = lx * ac - ly * as + ax;
        cay[i] = lx * as + ly * ac + ay;
        lx = CTX[i] * bdx; ly = CTY[i] * bdy;
        cbx[i] = lx * bc - ly * bs + bx;
        cby[i] = lx * bs + ly * bc + by;
    }

    float acc = edges_clip_acc(cax, cay, bx, by, 0.5f * bdx, 0.5f * bdy, bc, bs)
              + edges_clip_acc(cbx, cby, ax, ay, 0.5f * adx, 0.5f * ady, ac, as);
    return 0.5f * fabsf(acc);
}

__global__ void __launch_bounds__(BLOCK)
iou_loss_fused(const float* __restrict__ iou_pred,
               const int* __restrict__ mask,
               const int* __restrict__ ind,
               const float* __restrict__ box_pred,
               const float* __restrict__ box_gt,
               int M, int HW, int total,
               float* __restrict__ out, int out_size)
{
    int tid = blockIdx.x * BLOCK + threadIdx.x;
    float num = 0.0f, den = 0.0f;

    if (tid < total) {
        // all loads issued up front, unconditionally: mask never gates a
        // load, so the only serial chain is ind -> scattered gather.
        int mm  = mask[tid];
        int idx = ind[tid];
        int b = tid / M;

        float gb[7];
        const float* gp = box_gt + (size_t)tid * 7;
#pragma unroll
        for (int d = 0; d < 7; d++) gb[d] = gp[d];

        const float* bp = box_pred + (size_t)b * 7 * HW + idx;
        float pred = iou_pred[(size_t)b * HW + idx];
        float pb[7];
#pragma unroll
        for (int d = 0; d < 7; d++) pb[d] = bp[(size_t)d * HW];

        if (mm != 0) {
            // exact quick reject: separated bounding circles -> every edge
            // clips to an empty segment -> inter_bev exactly 0.
            float dx = pb[0] - gb[0], dy = pb[1] - gb[1];
            float ra2 = pb[3] * pb[3] + pb[4] * pb[4];
            float rb2 = gb[3] * gb[3] + gb[4] * gb[4];
            float rr = 0.5f * (__fsqrt_rn(ra2) + __fsqrt_rn(rb2)) + 1e-3f;

            float target;
            if (dx * dx + dy * dy > rr * rr) {
                target = -1.0f;   // iou = 0 -> 2*0-1
            } else {
                float inter_bev = bev_inter(pb[0], pb[1], pb[3], pb[4], pb[6],
                                            gb[0], gb[1], gb[3], gb[4], gb[6]);
                float top = fminf(pb[2] + pb[5] * 0.5f, gb[2] + gb[5] * 0.5f);
                float bot = fmaxf(pb[2] - pb[5] * 0.5f, gb[2] - gb[5] * 0.5f);
                float inter = inter_bev * fmaxf(top - bot, 0.0f);
                float va = pb[3] * pb[4] * pb[5];
                float vb = gb[3] * gb[4] * gb[5];
                float iou = inter / fmaxf(va + vb - inter, 1e-6f);
                target = 2.0f * iou - 1.0f;
            }

            num = fabsf(pred - target);
            den = 1.0f;
        }
    }

    // warp reduce
#pragma unroll
    for (int off = 16; off > 0; off >>= 1) {
        num += __shfl_down_sync(0xffffffffu, num, off);
        den += __shfl_down_sync(0xffffffffu, den, off);
    }
    __shared__ float2 swarp[BLOCK / 32];
    __shared__ bool s_last;
    int lane = threadIdx.x & 31, wid = threadIdx.x >> 5;
    if (lane == 0) swarp[wid] = make_float2(num, den);
    __syncthreads();

    if (threadIdx.x == 0) {
        float2 acc = swarp[0];
#pragma unroll
        for (int w = 1; w < BLOCK / 32; w++) {
            acc.x += swarp[w].x; acc.y += swarp[w].y;
        }
        g_partials[blockIdx.x] = acc;
        __threadfence();
        unsigned int v = atomicAdd(&g_count, 1u);
        s_last = (v == gridDim.x - 1);
    }
    __syncthreads();

    // last-finishing block: warp 0 alone reduces partials and writes out
    if (s_last && wid == 0) {
        float pn = 0.0f, pd = 0.0f;
        for (int i = lane; i < (int)gridDim.x; i += 32) {
            float2 p = g_partials[i];
            pn += p.x; pd += p.y;
        }
#pragma unroll
        for (int off = 16; off > 0; off >>= 1) {
            pn += __shfl_down_sync(0xffffffffu, pn, off);
            pd += __shfl_down_sync(0xffffffffu, pd, off);
        }
        if (lane == 0) {
            float loss = pn / (pd + 1e-4f);
            for (int i = 0; i < out_size; i++) out[i] = loss;
            g_count = 0;  // reset for next graph replay
        }
    }
}

extern "C" void kernel_launch(void* const* d_in, const int* in_sizes, int n_in,
                              void* d_out, int out_size)
{
    const float* iou_pred = (const float*)d_in[0];  // (B,1,H,W)
    const int*   mask     = (const int*)d_in[1];    // (B,M)
    const int*   ind      = (const int*)d_in[2];    // (B,M)
    const float* box_pred = (const float*)d_in[3];  // (B,7,H,W)
    const float* box_gt   = (const float*)d_in[4];  // (B,M,7)

    const int B = 16;
    int BM = in_sizes[1];     // B*M
    int M = BM / B;
    int HW = in_sizes[0] / B; // C == 1

    int total = BM;
    int nblocks = (total + BLOCK - 1) / BLOCK;
    if (nblocks > MAXBLOCKS) nblocks = MAXBLOCKS;  // 8000/64 = 125

    iou_loss_fused<<<nblocks, BLOCK>>>(iou_pred, mask, ind, box_pred, box_gt,
                                       M, HW, total, (float*)d_out, out_size);
}